// round 4
// baseline (speedup 1.0000x reference)
#include <cuda_runtime.h>
#include <cstdint>

// HighOrderFactorizationMachineModel: BATCH=16384, F=20 fields (dim 50000 each),
// EMBED_DIM=16, ORDER=3. emb_table row = 32 floats: [0:16) order-2 dims,
// [16:32) order-3 dims. Closed forms via power sums (Newton identities):
//   e2 = (p1^2 - p2)/2
//   e3 = (p1^3 - 3 p1 p2 + 2 p3)/6
//
// One warp per sample, lane l owns row element l (one coalesced 128B line per
// gather). R4 KEY CHANGE: ptxas kept refusing >32 regs and serializing the
// gathers (MLP~8). Now the 20 gathers are volatile inline-PTX ld.global.nc
// followed by a memory fence, and __launch_bounds__(256,3) lifts the register
// budget, forcing all 20 loads in flight (MLP=20) before any consumption.

#define FM_BATCH 16384
#define FM_F 20
#define FM_FIELD_DIM 50000

__global__ __launch_bounds__(256, 3)
void fm_ho_kernel(const int* __restrict__ x,
                  const float* __restrict__ emb,
                  const float* __restrict__ lin,
                  const float* __restrict__ bias,
                  float* __restrict__ out)
{
    const int warp = (blockIdx.x * blockDim.x + threadIdx.x) >> 5;
    const int lane = threadIdx.x & 31;
    const int s = warp;

    // 1) Index row: 20 ints = 80 bytes, 16B-aligned -> 5x int4 broadcast loads.
    int idx[FM_F];
    {
        const int4* xr = (const int4*)(x + s * FM_F);
        #pragma unroll
        for (int q = 0; q < FM_F / 4; q++) {
            const int4 t = __ldg(&xr[q]);
            idx[4 * q + 0] = t.x + (4 * q + 0) * FM_FIELD_DIM;
            idx[4 * q + 1] = t.y + (4 * q + 1) * FM_FIELD_DIM;
            idx[4 * q + 2] = t.z + (4 * q + 2) * FM_FIELD_DIM;
            idx[4 * q + 3] = t.w + (4 * q + 3) * FM_FIELD_DIM;
        }
    }

    // 2) 20 independent gathers, volatile PTX so they cannot be fused/sunk.
    float v[FM_F];
    #pragma unroll
    for (int f = 0; f < FM_F; f++) {
        const float* p = emb + (long)idx[f] * 32 + lane;
        asm volatile("ld.global.nc.f32 %0, [%1];" : "=f"(v[f]) : "l"(p));
    }
    // Linear-term gather rides on lanes 0..19.
    float linv = 0.0f;
    if (lane < FM_F) {
        const float* p = lin + idx[lane];
        asm volatile("ld.global.nc.f32 %0, [%1];" : "=f"(linv) : "l"(p));
    }
    asm volatile("" ::: "memory");  // all loads issued before any consume

    // 3) Power sums.
    float p1 = 0.0f, p2 = 0.0f, p3 = 0.0f;
    #pragma unroll
    for (int f = 0; f < FM_F; f++) {
        const float w = v[f];
        const float w2 = w * w;
        p1 += w;
        p2 += w2;
        p3 += w2 * w;
    }

    // Lanes 0..15: order-2 dims. Lanes 16..31: order-3 dims.
    float term;
    if (lane < 16) {
        term = 0.5f * (p1 * p1 - p2);
    } else {
        term = (p1 * p1 * p1 - 3.0f * p1 * p2 + 2.0f * p3) * (1.0f / 6.0f);
    }
    term += linv;   // lanes 0..19 contribute linear part, others add 0

    // Warp-wide sum.
    #pragma unroll
    for (int o = 16; o > 0; o >>= 1)
        term += __shfl_xor_sync(0xffffffffu, term, o);

    if (lane == 0)
        out[s] = term + __ldg(&bias[0]);
}

extern "C" void kernel_launch(void* const* d_in, const int* in_sizes, int n_in,
                              void* d_out, int out_size)
{
    const int*   x    = (const int*)d_in[0];
    const float* emb  = (const float*)d_in[1];
    const float* lin  = (const float*)d_in[2];
    const float* bias = (const float*)d_in[3];
    float*       out  = (float*)d_out;

    // 16384 samples, 1 warp each, 8 warps/block -> 2048 blocks.
    const int threads = 256;
    const int blocks  = (FM_BATCH * 32) / threads;
    fm_ho_kernel<<<blocks, threads>>>(x, emb, lin, bias, out);
}